// round 1
// baseline (speedup 1.0000x reference)
#include <cuda_runtime.h>
#include <cstdint>
#include <cstddef>

#define NE 8
#define TOPK 2
#define TT 4096
#define HH 2048
#define FF 8192
#define BM 128
#define BN 64
#define BK 16
#define MAXROWS (TT * TOPK + NE * BM)            /* 9216 padded pair rows */
#define MAXTILES ((TT * TOPK) / BM + NE)         /* 72 */

/* ------------------------------ scratch ------------------------------ */
__device__ float g_hact[(size_t)MAXROWS * FF];   /* SwiGLU activations   */
__device__ float g_y[(size_t)MAXROWS * HH];      /* per-pair expert out  */
__device__ int   g_counts[NE];
__device__ int   g_base[NE];
__device__ int   g_tileE[MAXTILES];
__device__ int   g_tilePr0[MAXTILES];
__device__ int   g_tileValid[MAXTILES];
__device__ int   g_ntiles;
__device__ int   g_tok[MAXROWS];                 /* pair row -> token    */
__device__ int   g_te[TT * TOPK];
__device__ float g_twt[TT * TOPK];
__device__ int   g_tpos[TT * TOPK];
__device__ int   g_trow[TT * TOPK];              /* token slot -> row    */

/* ------------------------------ helpers ------------------------------ */
__device__ __forceinline__ uint32_t f2tf32(float x) {
    uint32_t u;
    asm("cvt.rna.tf32.f32 %0, %1;" : "=r"(u) : "f"(x));
    return u;
}

__device__ __forceinline__ void mma8(float* d, const uint32_t* a,
                                     uint32_t b0, uint32_t b1) {
    asm volatile(
        "mma.sync.aligned.m16n8k8.row.col.f32.tf32.tf32.f32 "
        "{%0,%1,%2,%3}, {%4,%5,%6,%7}, {%8,%9}, {%0,%1,%2,%3};\n"
        : "+f"(d[0]), "+f"(d[1]), "+f"(d[2]), "+f"(d[3])
        : "r"(a[0]), "r"(a[1]), "r"(a[2]), "r"(a[3]), "r"(b0), "r"(b1));
}

/* ------------------------------ kernels ------------------------------ */
__global__ void zero_kernel() {
    if (threadIdx.x < NE) g_counts[threadIdx.x] = 0;
}

__global__ __launch_bounds__(128)
void router_kernel(const float* __restrict__ hs, const float* __restrict__ gw) {
    __shared__ float Xs[128][33];
    __shared__ float Gs[8][33];
    const int tid = threadIdx.x;
    const int tok0 = blockIdx.x * 128;

    float acc[NE];
#pragma unroll
    for (int e = 0; e < NE; e++) acc[e] = 0.f;

    for (int kc = 0; kc < HH; kc += 32) {
#pragma unroll
        for (int j = 0; j < 8; j++) {
            int idx = j * 128 + tid;       /* float4 index, 0..1023 */
            int r = idx >> 3;
            int c4 = (idx & 7) * 4;
            float4 v = *(const float4*)&hs[(size_t)(tok0 + r) * HH + kc + c4];
            Xs[r][c4 + 0] = v.x; Xs[r][c4 + 1] = v.y;
            Xs[r][c4 + 2] = v.z; Xs[r][c4 + 3] = v.w;
        }
        if (tid < 64) {
            int r = tid >> 3;
            int c4 = (tid & 7) * 4;
            float4 v = *(const float4*)&gw[(size_t)r * HH + kc + c4];
            Gs[r][c4 + 0] = v.x; Gs[r][c4 + 1] = v.y;
            Gs[r][c4 + 2] = v.z; Gs[r][c4 + 3] = v.w;
        }
        __syncthreads();
#pragma unroll
        for (int c = 0; c < 32; c++) {
            float x = Xs[tid][c];
#pragma unroll
            for (int e = 0; e < NE; e++) acc[e] += x * Gs[e][c];
        }
        __syncthreads();
    }

    /* softmax over 8 logits + top-2 + renormalize */
    float mx = acc[0];
#pragma unroll
    for (int e = 1; e < NE; e++) mx = fmaxf(mx, acc[e]);
    float p[NE];
    float s = 0.f;
#pragma unroll
    for (int e = 0; e < NE; e++) { p[e] = expf(acc[e] - mx); s += p[e]; }
    (void)s; /* renorm ratio is s-independent */

    int i1 = 0;
#pragma unroll
    for (int e = 1; e < NE; e++) if (p[e] > p[i1]) i1 = e;
    int i2 = (i1 == 0) ? 1 : 0;
#pragma unroll
    for (int e = 0; e < NE; e++) if (e != i1 && p[e] > p[i2]) i2 = e;

    float wa = p[i1], wb = p[i2];
    float inv = 1.f / (wa + wb);
    int t = tok0 + tid;
    int pos0 = atomicAdd(&g_counts[i1], 1);
    int pos1 = atomicAdd(&g_counts[i2], 1);
    g_te[t * 2 + 0] = i1; g_twt[t * 2 + 0] = wa * inv; g_tpos[t * 2 + 0] = pos0;
    g_te[t * 2 + 1] = i2; g_twt[t * 2 + 1] = wb * inv; g_tpos[t * 2 + 1] = pos1;
}

__global__ void scan_kernel() {
    if (threadIdx.x != 0) return;
    int b = 0, t = 0;
    for (int e = 0; e < NE; e++) {
        int cnt = g_counts[e];
        g_base[e] = b;
        int tiles = (cnt + BM - 1) / BM;
        for (int i = 0; i < tiles; i++) {
            g_tileE[t] = e;
            g_tilePr0[t] = b + i * BM;
            g_tileValid[t] = min(BM, cnt - i * BM);
            t++;
        }
        b += tiles * BM;
    }
    g_ntiles = t;
}

__global__ void build_kernel() {
    int t = blockIdx.x * blockDim.x + threadIdx.x;
    if (t >= TT) return;
#pragma unroll
    for (int s = 0; s < 2; s++) {
        int e = g_te[t * 2 + s];
        int row = g_base[e] + g_tpos[t * 2 + s];
        g_tok[row] = t;
        g_trow[t * 2 + s] = row;
    }
}

/* GEMM1: act[pair, F] = silu(X w1^T) * (X w3^T); A gathered via g_tok.
   grid.x = tile (so all tiles of same n-column run concurrently -> weight
   tiles get L2 reuse), grid.y = F/BN. */
__global__ __launch_bounds__(256, 2)
void gemm1_kernel(const float* __restrict__ hs, const float* __restrict__ w1g,
                  const float* __restrict__ w3g) {
    const int tile = blockIdx.x;
    if (tile >= g_ntiles) return;
    const int e = g_tileE[tile];
    const int pr0 = g_tilePr0[tile];
    const int valid = g_tileValid[tile];
    const int n0 = blockIdx.y * BN;

    __shared__ uint32_t As[BM][20];      /* stride 20: conflict-free frags */
    __shared__ uint32_t Bs[2][BN][20];

    const int tid = threadIdx.x;
    const int lane = tid & 31;
    const int wid = tid >> 5;
    const int wm = (wid & 3) * 32;
    const int wn = (wid >> 2) * 32;

    float acc[2][2][4][4];
#pragma unroll
    for (int m = 0; m < 2; m++)
#pragma unroll
        for (int mt = 0; mt < 2; mt++)
#pragma unroll
            for (int nt = 0; nt < 4; nt++)
#pragma unroll
                for (int i = 0; i < 4; i++) acc[m][mt][nt][i] = 0.f;

    const int ar = tid >> 2;            /* 0..63 */
    const int kq = (tid & 3) * 4;       /* 0,4,8,12 */

    const float* aptr0 = (ar < valid)
        ? hs + (size_t)g_tok[pr0 + ar] * HH + kq : (const float*)0;
    const float* aptr1 = (ar + 64 < valid)
        ? hs + (size_t)g_tok[pr0 + ar + 64] * HH + kq : (const float*)0;
    const float* bptr0 = w1g + ((size_t)e * FF + n0 + ar) * HH + kq;
    const float* bptr1 = w3g + ((size_t)e * FF + n0 + ar) * HH + kq;

    const float4 zz = make_float4(0.f, 0.f, 0.f, 0.f);
    float4 av0, av1, bv0, bv1;

    av0 = aptr0 ? *(const float4*)aptr0 : zz;
    av1 = aptr1 ? *(const float4*)aptr1 : zz;
    bv0 = *(const float4*)bptr0;
    bv1 = *(const float4*)bptr1;

#define G1_STORE()                                                       \
    do {                                                                 \
        As[ar][kq + 0] = f2tf32(av0.x); As[ar][kq + 1] = f2tf32(av0.y);  \
        As[ar][kq + 2] = f2tf32(av0.z); As[ar][kq + 3] = f2tf32(av0.w);  \
        As[ar + 64][kq + 0] = f2tf32(av1.x);                             \
        As[ar + 64][kq + 1] = f2tf32(av1.y);                             \
        As[ar + 64][kq + 2] = f2tf32(av1.z);                             \
        As[ar + 64][kq + 3] = f2tf32(av1.w);                             \
        Bs[0][ar][kq + 0] = f2tf32(bv0.x); Bs[0][ar][kq + 1] = f2tf32(bv0.y); \
        Bs[0][ar][kq + 2] = f2tf32(bv0.z); Bs[0][ar][kq + 3] = f2tf32(bv0.w); \
        Bs[1][ar][kq + 0] = f2tf32(bv1.x); Bs[1][ar][kq + 1] = f2tf32(bv1.y); \
        Bs[1][ar][kq + 2] = f2tf32(bv1.z); Bs[1][ar][kq + 3] = f2tf32(bv1.w); \
    } while (0)

    G1_STORE();
    __syncthreads();

    const int KT = HH / BK;  /* 128 */
    for (int kt = 1; kt <= KT; kt++) {
        if (kt < KT) {
            int k0 = kt * BK;
            av0 = aptr0 ? *(const float4*)(aptr0 + k0) : zz;
            av1 = aptr1 ? *(const float4*)(aptr1 + k0) : zz;
            bv0 = *(const float4*)(bptr0 + k0);
            bv1 = *(const float4*)(bptr1 + k0);
        }
#pragma unroll
        for (int kk = 0; kk < BK; kk += 8) {
            uint32_t af[2][4];
#pragma unroll
            for (int mt = 0; mt < 2; mt++) {
                int r = wm + mt * 16 + (lane >> 2);
                int c = kk + (lane & 3);
                af[mt][0] = As[r][c];
                af[mt][1] = As[r + 8][c];
                af[mt][2] = As[r][c + 4];
                af[mt][3] = As[r + 8][c + 4];
            }
#pragma unroll
            for (int nt = 0; nt < 4; nt++) {
                int n = wn + nt * 8 + (lane >> 2);
                int kb = kk + (lane & 3);
                uint32_t b00 = Bs[0][n][kb], b01 = Bs[0][n][kb + 4];
                uint32_t b10 = Bs[1][n][kb], b11 = Bs[1][n][kb + 4];
                mma8(acc[0][0][nt], af[0], b00, b01);
                mma8(acc[0][1][nt], af[1], b00, b01);
                mma8(acc[1][0][nt], af[0], b10, b11);
                mma8(acc[1][1][nt], af[1], b10, b11);
            }
        }
        __syncthreads();
        if (kt < KT) {
            G1_STORE();
            __syncthreads();
        }
    }
#undef G1_STORE

    /* epilogue: SwiGLU, write fp32 activations */
#pragma unroll
    for (int mt = 0; mt < 2; mt++) {
#pragma unroll
        for (int nt = 0; nt < 4; nt++) {
            int r = wm + mt * 16 + (lane >> 2);
            int c = n0 + wn + nt * 8 + (lane & 3) * 2;
#pragma unroll
            for (int h = 0; h < 2; h++) {
                int row = r + h * 8;
                float a0 = acc[0][mt][nt][h * 2 + 0];
                float a1 = acc[0][mt][nt][h * 2 + 1];
                float g0 = acc[1][mt][nt][h * 2 + 0];
                float g1 = acc[1][mt][nt][h * 2 + 1];
                float s0 = (a0 / (1.f + __expf(-a0))) * g0;
                float s1 = (a1 / (1.f + __expf(-a1))) * g1;
                *(float2*)&g_hact[(size_t)(pr0 + row) * FF + c] =
                    make_float2(s0, s1);
            }
        }
    }
}

/* GEMM2: y[pair, H] = act @ w2^T. grid.x = H/BN, grid.y = tile (so all
   n-columns of the same activation tile run concurrently -> A L2 reuse). */
__global__ __launch_bounds__(256, 2)
void gemm2_kernel(const float* __restrict__ w2g) {
    const int tile = blockIdx.y;
    if (tile >= g_ntiles) return;
    const int e = g_tileE[tile];
    const int pr0 = g_tilePr0[tile];
    const int valid = g_tileValid[tile];
    const int n0 = blockIdx.x * BN;

    __shared__ uint32_t As[BM][20];
    __shared__ uint32_t Bs[BN][20];

    const int tid = threadIdx.x;
    const int lane = tid & 31;
    const int wid = tid >> 5;
    const int wm = (wid & 3) * 32;
    const int wn = (wid >> 2) * 32;

    float acc[2][4][4];
#pragma unroll
    for (int mt = 0; mt < 2; mt++)
#pragma unroll
        for (int nt = 0; nt < 4; nt++)
#pragma unroll
            for (int i = 0; i < 4; i++) acc[mt][nt][i] = 0.f;

    const int ar = tid >> 2;
    const int kq = (tid & 3) * 4;

    const float* aptr0 = (ar < valid)
        ? g_hact + (size_t)(pr0 + ar) * FF + kq : (const float*)0;
    const float* aptr1 = (ar + 64 < valid)
        ? g_hact + (size_t)(pr0 + ar + 64) * FF + kq : (const float*)0;
    const float* bptr = w2g + ((size_t)e * HH + n0 + ar) * FF + kq;

    const float4 zz = make_float4(0.f, 0.f, 0.f, 0.f);
    float4 av0, av1, bv;

    av0 = aptr0 ? *(const float4*)aptr0 : zz;
    av1 = aptr1 ? *(const float4*)aptr1 : zz;
    bv = *(const float4*)bptr;

#define G2_STORE()                                                       \
    do {                                                                 \
        As[ar][kq + 0] = f2tf32(av0.x); As[ar][kq + 1] = f2tf32(av0.y);  \
        As[ar][kq + 2] = f2tf32(av0.z); As[ar][kq + 3] = f2tf32(av0.w);  \
        As[ar + 64][kq + 0] = f2tf32(av1.x);                             \
        As[ar + 64][kq + 1] = f2tf32(av1.y);                             \
        As[ar + 64][kq + 2] = f2tf32(av1.z);                             \
        As[ar + 64][kq + 3] = f2tf32(av1.w);                             \
        Bs[ar][kq + 0] = f2tf32(bv.x); Bs[ar][kq + 1] = f2tf32(bv.y);    \
        Bs[ar][kq + 2] = f2tf32(bv.z); Bs[ar][kq + 3] = f2tf32(bv.w);    \
    } while (0)

    G2_STORE();
    __syncthreads();

    const int KT = FF / BK;  /* 512 */
    for (int kt = 1; kt <= KT; kt++) {
        if (kt < KT) {
            int k0 = kt * BK;
            av0 = aptr0 ? *(const float4*)(aptr0 + k0) : zz;
            av1 = aptr1 ? *(const float4*)(aptr1 + k0) : zz;
            bv = *(const float4*)(bptr + k0);
        }
#pragma unroll
        for (int kk = 0; kk < BK; kk += 8) {
            uint32_t af[2][4];
#pragma unroll
            for (int mt = 0; mt < 2; mt++) {
                int r = wm + mt * 16 + (lane >> 2);
                int c = kk + (lane & 3);
                af[mt][0] = As[r][c];
                af[mt][1] = As[r + 8][c];
                af[mt][2] = As[r][c + 4];
                af[mt][3] = As[r + 8][c + 4];
            }
#pragma unroll
            for (int nt = 0; nt < 4; nt++) {
                int n = wn + nt * 8 + (lane >> 2);
                int kb = kk + (lane & 3);
                uint32_t b0 = Bs[n][kb], b1 = Bs[n][kb + 4];
                mma8(acc[0][nt], af[0], b0, b1);
                mma8(acc[1][nt], af[1], b0, b1);
            }
        }
        __syncthreads();
        if (kt < KT) {
            G2_STORE();
            __syncthreads();
        }
    }
#undef G2_STORE

#pragma unroll
    for (int mt = 0; mt < 2; mt++) {
#pragma unroll
        for (int nt = 0; nt < 4; nt++) {
            int r = wm + mt * 16 + (lane >> 2);
            int c = n0 + wn + nt * 8 + (lane & 3) * 2;
#pragma unroll
            for (int h = 0; h < 2; h++) {
                int row = r + h * 8;
                *(float2*)&g_y[(size_t)(pr0 + row) * HH + c] =
                    make_float2(acc[mt][nt][h * 2 + 0], acc[mt][nt][h * 2 + 1]);
            }
        }
    }
}

/* deterministic combine: out = w0*y[row0] + w1*y[row1] (full overwrite) */
__global__ __launch_bounds__(256)
void combine_kernel(float* __restrict__ out) {
    int idx = blockIdx.x * blockDim.x + threadIdx.x;  /* 0 .. T*H/4 */
    int t = idx >> 9;                /* HH/4 = 512 */
    int h4 = (idx & 511) << 2;
    int r0 = g_trow[t * 2 + 0], r1 = g_trow[t * 2 + 1];
    float w0 = g_twt[t * 2 + 0], w1 = g_twt[t * 2 + 1];
    float4 y0 = *(const float4*)&g_y[(size_t)r0 * HH + h4];
    float4 y1 = *(const float4*)&g_y[(size_t)r1 * HH + h4];
    float4 o;
    o.x = w0 * y0.x + w1 * y1.x;
    o.y = w0 * y0.y + w1 * y1.y;
    o.z = w0 * y0.z + w1 * y1.z;
    o.w = w0 * y0.w + w1 * y1.w;
    *(float4*)&out[(size_t)t * HH + h4] = o;
}

/* ------------------------------ launch ------------------------------- */
extern "C" void kernel_launch(void* const* d_in, const int* in_sizes, int n_in,
                              void* d_out, int out_size) {
    const float* hs = (const float*)d_in[0];
    const float* gw = (const float*)d_in[1];
    const float* w1 = (const float*)d_in[2];
    const float* w2 = (const float*)d_in[3];
    const float* w3 = (const float*)d_in[4];
    float* out = (float*)d_out;

    zero_kernel<<<1, 32>>>();
    router_kernel<<<TT / 128, 128>>>(hs, gw);
    scan_kernel<<<1, 32>>>();
    build_kernel<<<TT / 256, 256>>>();
    {
        dim3 g(MAXTILES, FF / BN);
        gemm1_kernel<<<g, 256>>>(hs, w1, w3);
    }
    {
        dim3 g(HH / BN, MAXTILES);
        gemm2_kernel<<<g, 256>>>(w2);
    }
    combine_kernel<<<(TT * HH / 4) / 256, 256>>>(out);
}